// round 11
// baseline (speedup 1.0000x reference)
#include <cuda_runtime.h>
#include <math.h>

#define BATCH   8
#define TAPS    128     // max row width: 3k+1 (+3 for C-conv) <= 128 for k <= 40
#define NROWS   45      // W_0..W_44 -> supports n_steps <= 88
#define SMAX    96      // window index range in apply grid (n_steps+1 <= 89)
#define NTW     128     // threads per window block
#define NTB     512     // threads in build_taps

// Operator powers W_k = M^k, width 3k+1. Row k serves steps 2k and 2k+1.
__device__ float g_taps[NROWS][TAPS];

// ---------------------------------------------------------------------------
// Zero the whole output (out_size divisible by 4). Atomic accumulation base.
// ---------------------------------------------------------------------------
__global__ void fill_zero(float* __restrict__ out, int n4)
{
    int i = blockIdx.x * blockDim.x + threadIdx.x;
    if (i < n4) ((float4*)out)[i] = make_float4(0.f, 0.f, 0.f, 0.f);
}

// ---------------------------------------------------------------------------
// Build W_k = M^k for k=0..K by log-depth doubling (6 barriers, not 40
// dependent shfl stages):  stage j:  W_{2^j + i} = W_{2^j} (*) W_i, i=1..2^j.
// M = A conv B is the same 4-tap operator for both traveling-wave chains
// (conv of fixed FIRs commutes). Rows in smem, left-padded 128 zeros so
// src[t-d] never needs a guard. Targets (> 2^j) never alias sources (<= 2^j).
// ---------------------------------------------------------------------------
__global__ void __launch_bounds__(NTB)
build_taps(const int* __restrict__ lengthp,
           const float* __restrict__ pluckp,
           const float* __restrict__ ngp,
           const float* __restrict__ bgp, int T)
{
    __shared__ float sW[NROWS][256];    // tap t of row r at sW[r][128+t]
    const int tid = threadIdx.x;

    const int   length = lengthp[0];
    const float ng     = ngp[0];
    const float bg     = bgp[0];

    int n_steps = T / length;
    if (n_steps > 2 * (NROWS - 1)) n_steps = 2 * (NROWS - 1);
    const int K = n_steps >> 1;          // highest W row needed (<= 44)

    const float p      = pluckp[0];
    const float stringL = (float)length - 0.11f;
    const float dU2 = 2.0f * (stringL * p);
    const float dD2 = 2.0f * (stringL * (1.0f - p));
    const float f1 = dU2 - floorf(dU2);
    const float f2 = dD2 - floorf(dD2);
    const float bscale = (-bg) * 0.5f;

    const float a0 = -ng * (1.0f - f1), a1 = -ng * f1;
    const float b0 = bscale * (1.0f - f2), b1 = bscale, b2 = bscale * f2;
    const float m0 = a0 * b0;
    const float m1 = a0 * b1 + a1 * b0;
    const float m2 = a0 * b2 + a1 * b1;
    const float m3 = a1 * b2;

    // zero smem, seed W0 = delta, W1 = M
    for (int i = tid; i < NROWS * 256; i += NTB)
        ((float*)sW)[i] = 0.f;
    __syncthreads();
    if (tid == 0) {
        sW[0][128] = 1.0f;
        if (K >= 1) {
            sW[1][128] = m0; sW[1][129] = m1; sW[1][130] = m2; sW[1][131] = m3;
        }
    }
    __syncthreads();

    for (int j = 0; (1 << j) < K; ++j) {
        const int pj   = 1 << j;
        const int len  = 3 * pj + 1;             // width of W_pj (<= 97)
        const int nnew = min(pj, K - pj);        // targets pj+1 .. pj+nnew
        // work item = (source row, 4-tap chunk); chunk t0 <= 124, so the
        // widest read is sW[i][128+124+3] = [255] and deepest is [128+t0-96].
        for (int idx = tid; idx < nnew * 32; idx += NTB) {
            const int i  = (idx >> 5) + 1;       // source row 1..nnew
            const int t0 = (idx & 31) * 4;
            const int nrow = pj + i;
            if (t0 > 3 * nrow) continue;         // beyond target width
            const float* __restrict__ cw  = &sW[pj][128];
            const float* __restrict__ src = &sW[i][128 + t0];
            float acc0 = 0.f, acc1 = 0.f, acc2 = 0.f, acc3 = 0.f;
            #pragma unroll 4
            for (int d = 0; d < len; ++d) {
                const float c = cw[d];
                acc0 += c * src[0 - d];
                acc1 += c * src[1 - d];
                acc2 += c * src[2 - d];
                acc3 += c * src[3 - d];
            }
            sW[nrow][128 + t0]     = acc0;
            sW[nrow][128 + t0 + 1] = acc1;
            sW[nrow][128 + t0 + 2] = acc2;
            sW[nrow][128 + t0 + 3] = acc3;
        }
        __syncthreads();
    }

    // copy rows 0..K to global
    for (int i = tid; i < (K + 1) * TAPS; i += NTB)
        g_taps[i >> 7][i & 127] = sW[i >> 7][128 + (i & 127)];
}

// ---------------------------------------------------------------------------
// One block per window (z, b, s). Row taps reconstructed on the fly:
// h_s = C (*) W_{s>>1}, C = h0^ci (even s) or X^ci (*) h0^ci (odd s), <= 4
// coefficients. conv(taps, excitation): support w+255 <= 381, 3 outputs per
// thread at stride 128 (conflict-free LDS, uniform loop). Any output address
// is covered by <= 2 windows (s->s+2 spacing = i1+i2 ~ 2*stringL > 2*381),
// so 2-operand fp atomicAdd onto a zeroed buffer is deterministic.
// ---------------------------------------------------------------------------
__global__ void __launch_bounds__(NTW)
apply_window(const int* __restrict__ lengthp,
             const float* __restrict__ pluckp,
             const float* __restrict__ ngp,
             const float* __restrict__ bgp,
             const float* __restrict__ exc,
             float* __restrict__ out, int T)
{
    const int blk = blockIdx.x;
    const int s   = blk % SMAX;
    const int rb  = blk / SMAX;         // 0..15
    const int z   = rb >> 3;            // 0 = sl rows, 1 = sr rows
    const int b   = rb & 7;
    const int tid = threadIdx.x;

    const int length = lengthp[0];
    int n_steps = T / length;
    if (n_steps > 2 * (NROWS - 1)) n_steps = 2 * (NROWS - 1);
    if (s > n_steps) return;            // surplus window: block-uniform exit

    const float p      = pluckp[0];
    const float stringL = (float)length - 0.11f;
    const float nUp     = stringL * p;
    const float nDown   = stringL * (1.0f - p);
    const int iU = (int)floorf(nUp);
    const int iD = (int)floorf(nDown);
    const float dU2 = 2.0f * nUp;   const float f1 = dU2 - floorf(dU2);
    const float dD2 = 2.0f * nDown; const float f2 = dD2 - floorf(dD2);
    const int i1 = (int)dU2;
    const int i2 = (int)dD2;

    const int ci = (s & 1) ^ z;
    const int ha = (s + 1) >> 1, hb = s >> 1;
    int off, w;
    if (ci == 0) { off = iU + ha * i1 + hb * i2; w = 2 + ha + 2 * hb; }
    else         { off = iD + ha * i2 + hb * i1; w = 2 + 2 * ha + hb; }
    if (w > TAPS) w = TAPS;
    if (off >= T) return;               // window beyond buffer: uniform exit

    __shared__ float est[512];          // est[128 + e], e in [-128, 384); zero-padded
    __shared__ float taps[TAPS];

    est[tid] = 0.f;                     // e in [-128, 0)
    est[384 + tid] = 0.f;               // e in [256, 384)
    {
        const float* __restrict__ x = exc + (size_t)b * T;
        const int ne = min(256, T);     // excitation support is [0,256)
        est[128 + tid]       = (tid       < ne) ? x[tid]       : 0.f;
        est[128 + 128 + tid] = (tid + 128 < ne) ? x[tid + 128] : 0.f;
    }

    // C = coefficient conv (<= 4 taps): h0 for even s, X (*) h0 for odd s.
    {
        const float fU = nUp   - floorf(nUp);
        const float fD = nDown - floorf(nDown);
        const float fr = ci ? fD : fU;
        const float h0c0 = (1.0f - fr) * 0.5f;
        const float h0c1 = fr * 0.5f;
        float C0, C1, C2, C3;
        if (s & 1) {
            if (ci == 0) {              // A (*) h0
                const float ng = ngp[0];
                const float a0 = -ng * (1.0f - f1), a1 = -ng * f1;
                C0 = a0 * h0c0; C1 = a0 * h0c1 + a1 * h0c0; C2 = a1 * h0c1; C3 = 0.f;
            } else {                    // B (*) h0
                const float bg = bgp[0];
                const float bs = (-bg) * 0.5f;
                const float b0 = bs * (1.0f - f2), b1 = bs, b2 = bs * f2;
                C0 = b0 * h0c0; C1 = b0 * h0c1 + b1 * h0c0;
                C2 = b1 * h0c1 + b2 * h0c0; C3 = b2 * h0c1;
            }
        } else {
            C0 = h0c0; C1 = h0c1; C2 = 0.f; C3 = 0.f;
        }
        const float* __restrict__ W = g_taps[s >> 1];
        float w0 = W[tid];
        float w1 = (tid >= 1) ? W[tid - 1] : 0.f;
        float w2 = (tid >= 2) ? W[tid - 2] : 0.f;
        float w3 = (tid >= 3) ? W[tid - 3] : 0.f;
        taps[tid] = C0 * w0 + C1 * w1 + C2 * w2 + C3 * w3;
    }
    __syncthreads();

    float a0 = 0.f, a1 = 0.f, a2 = 0.f;
    const float* e0 = &est[128 + tid];
    #pragma unroll 4
    for (int j = 0; j < w; ++j) {
        float h = taps[j];
        a0 += h * e0[-j];
        a1 += h * e0[128 - j];
        a2 += h * e0[256 - j];
    }

    const int sup = w + 255;            // conv support length
    float* __restrict__ row = out + (size_t)(z * BATCH + b) * T;
    const int t0 = off + tid;
    if (tid       < sup && t0       < T) atomicAdd(&row[t0],       a0);
    if (tid + 128 < sup && t0 + 128 < T) atomicAdd(&row[t0 + 128], a1);
    if (tid + 256 < sup && t0 + 256 < T) atomicAdd(&row[t0 + 256], a2);
}

extern "C" void kernel_launch(void* const* d_in, const int* in_sizes, int n_in,
                              void* d_out, int out_size)
{
    const int*   lengthp = (const int*)  d_in[0];
    const float* pluckp  = (const float*)d_in[1];
    const float* exc     = (const float*)d_in[2];
    const float* ngp     = (const float*)d_in[3];
    const float* bgp     = (const float*)d_in[4];
    float* out = (float*)d_out;

    const int T  = in_sizes[2] / BATCH;          // excitation is (8, T)
    const int n4 = out_size / 4;

    build_taps<<<1, NTB>>>(lengthp, pluckp, ngp, bgp, T);
    fill_zero<<<(n4 + 255) / 256, 256>>>(out, n4);
    apply_window<<<2 * BATCH * SMAX, NTW>>>(lengthp, pluckp, ngp, bgp, exc, out, T);
}

// round 12
// speedup vs baseline: 1.4915x; 1.4915x over previous
#include <cuda_runtime.h>
#include <math.h>

#define BATCH    8
#define TAPS     128    // row width 3k+1 <= 121 for k <= 40; +3 C-conv <= 124
#define NROWBLK  41     // rows k = 0..40  (n_steps <= 80)
#define SMAX     81     // windows s = 0..80
#define NTW      128
#define FILLPB   512    // float4 per fill block (128 thr x 4)

// Operator powers W_k = M^k. Row k serves steps 2k and 2k+1.
__device__ float g_taps[NROWBLK][TAPS];

// ---------------------------------------------------------------------------
// Kernel 1: blocks 0..40 each build one row W_k = M^k by per-block repeated
// squaring (squarings P->P*P, one product-conv per set bit of k; <= 7
// barrier-separated convs, ~220 FMA-terms/thread). Blocks >= NROWBLK zero
// the output buffer concurrently. M = A conv B is chain-independent.
// ---------------------------------------------------------------------------
__global__ void __launch_bounds__(NTW)
rows_and_fill(const int* __restrict__ lengthp,
              const float* __restrict__ pluckp,
              const float* __restrict__ ngp,
              const float* __restrict__ bgp,
              float* __restrict__ out, int n4, int T)
{
    const int tid = threadIdx.x;

    if (blockIdx.x >= NROWBLK) {
        const int base = (blockIdx.x - NROWBLK) * FILLPB + tid;
        const float4 z4 = make_float4(0.f, 0.f, 0.f, 0.f);
        #pragma unroll
        for (int i = 0; i < 4; ++i) {
            int idx = base + i * NTW;
            if (idx < n4) ((float4*)out)[idx] = z4;
        }
        return;
    }

    const int k = blockIdx.x;           // row index (block-uniform)
    const int length = lengthp[0];
    int n_steps = T / length;
    if (n_steps > 80) n_steps = 80;
    if (k > (n_steps >> 1)) return;     // unused row: uniform exit

    // M = A conv B
    const float p  = pluckp[0];
    const float ng = ngp[0];
    const float bg = bgp[0];
    const float stringL = (float)length - 0.11f;
    const float dU2 = 2.0f * (stringL * p);
    const float dD2 = 2.0f * (stringL * (1.0f - p));
    const float f1 = dU2 - floorf(dU2);
    const float f2 = dD2 - floorf(dD2);
    const float bscale = (-bg) * 0.5f;
    const float a0 = -ng * (1.0f - f1), a1 = -ng * f1;
    const float b0 = bscale * (1.0f - f2), b1 = bscale, b2 = bscale * f2;
    const float m0 = a0 * b0;
    const float m1 = a0 * b1 + a1 * b0;
    const float m2 = a0 * b2 + a1 * b1;
    const float m3 = a1 * b2;

    // Buffers left-padded with 128 zeros: tap t at buf[128+t].
    __shared__ float bufA[256], bufB[256], bufP[256], bufQ[256];
    bufA[tid] = 0.f; bufA[128 + tid] = 0.f;
    bufB[tid] = 0.f; bufB[128 + tid] = 0.f;
    bufP[tid] = 0.f; bufP[128 + tid] = 0.f;
    bufQ[tid] = 0.f; bufQ[128 + tid] = 0.f;
    __syncthreads();
    if (tid == 0) {
        bufA[128] = 1.0f;               // cur = delta
        bufP[128] = m0; bufP[129] = m1; bufP[130] = m2; bufP[131] = m3;
    }
    __syncthreads();

    float *cur = bufA, *curN = bufB, *Pc = bufP, *Pn = bufQ;
    int rem = k;
    int lenP = 4;                       // width of P = M^(2^j): 4,7,13,25,49,97
    while (rem) {
        if (rem & 1) {                  // cur = cur (*) P
            float acc = 0.f;
            const float* pc = Pc + 128;
            const float* cu = cur + 128 + tid;
            for (int d = 0; d < lenP; ++d) acc += pc[d] * cu[-d];
            curN[128 + tid] = acc;      // distinct buffer: no read/write race
            float* t = cur; cur = curN; curN = t;
            __syncthreads();
        }
        rem >>= 1;
        if (rem) {                      // P = P (*) P
            float acc = 0.f;
            const float* pc = Pc + 128;
            for (int d = 0; d < lenP; ++d) acc += pc[d] * pc[tid - d];
            Pn[128 + tid] = acc;
            float* t = Pc; Pc = Pn; Pn = t;
            lenP = 2 * lenP - 1;
            __syncthreads();
        }
    }

    g_taps[k][tid] = cur[128 + tid];
}

// ---------------------------------------------------------------------------
// Kernel 2 (verbatim logic from R11): one block per window (z, b, s).
// Row taps reconstructed on the fly: h_s = C (*) W_{s>>1}, C <= 4 coeffs
// (h0 for even s; X (*) h0 for odd s). conv(taps, excitation): support
// w+255 <= 378, 3 outputs/thread stride 128 (conflict-free LDS, uniform
// loop). Any output address is covered by <= 2 windows (s->s+2 spacing =
// i1+i2 ~ 2*stringL > 2*378), so 2-operand fp atomicAdd onto a zeroed
// buffer is order-independent -> deterministic.
// ---------------------------------------------------------------------------
__global__ void __launch_bounds__(NTW)
apply_window(const int* __restrict__ lengthp,
             const float* __restrict__ pluckp,
             const float* __restrict__ ngp,
             const float* __restrict__ bgp,
             const float* __restrict__ exc,
             float* __restrict__ out, int T)
{
    const int blk = blockIdx.x;
    const int s   = blk % SMAX;
    const int rb  = blk / SMAX;         // 0..15
    const int z   = rb >> 3;            // 0 = sl rows, 1 = sr rows
    const int b   = rb & 7;
    const int tid = threadIdx.x;

    const int length = lengthp[0];
    int n_steps = T / length;
    if (n_steps > 80) n_steps = 80;
    if (s > n_steps) return;            // surplus window: block-uniform exit

    const float p      = pluckp[0];
    const float stringL = (float)length - 0.11f;
    const float nUp     = stringL * p;
    const float nDown   = stringL * (1.0f - p);
    const int iU = (int)floorf(nUp);
    const int iD = (int)floorf(nDown);
    const float dU2 = 2.0f * nUp;   const float f1 = dU2 - floorf(dU2);
    const float dD2 = 2.0f * nDown; const float f2 = dD2 - floorf(dD2);
    const int i1 = (int)dU2;
    const int i2 = (int)dD2;

    const int ci = (s & 1) ^ z;
    const int ha = (s + 1) >> 1, hb = s >> 1;
    int off, w;
    if (ci == 0) { off = iU + ha * i1 + hb * i2; w = 2 + ha + 2 * hb; }
    else         { off = iD + ha * i2 + hb * i1; w = 2 + 2 * ha + hb; }
    if (w > TAPS) w = TAPS;
    if (off >= T) return;               // window beyond buffer: uniform exit

    __shared__ float est[512];          // est[128 + e], e in [-128, 384); zero-padded
    __shared__ float taps[TAPS];

    est[tid] = 0.f;                     // e in [-128, 0)
    est[384 + tid] = 0.f;               // e in [256, 384)
    {
        const float* __restrict__ x = exc + (size_t)b * T;
        const int ne = min(256, T);     // excitation support is [0,256)
        est[128 + tid]       = (tid       < ne) ? x[tid]       : 0.f;
        est[128 + 128 + tid] = (tid + 128 < ne) ? x[tid + 128] : 0.f;
    }

    // C = coefficient conv (<= 4 taps): h0 for even s, X (*) h0 for odd s.
    {
        const float fU = nUp   - floorf(nUp);
        const float fD = nDown - floorf(nDown);
        const float fr = ci ? fD : fU;
        const float h0c0 = (1.0f - fr) * 0.5f;
        const float h0c1 = fr * 0.5f;
        float C0, C1, C2, C3;
        if (s & 1) {
            if (ci == 0) {              // A (*) h0
                const float ng = ngp[0];
                const float a0 = -ng * (1.0f - f1), a1 = -ng * f1;
                C0 = a0 * h0c0; C1 = a0 * h0c1 + a1 * h0c0; C2 = a1 * h0c1; C3 = 0.f;
            } else {                    // B (*) h0
                const float bg = bgp[0];
                const float bs = (-bg) * 0.5f;
                const float b0 = bs * (1.0f - f2), b1 = bs, b2 = bs * f2;
                C0 = b0 * h0c0; C1 = b0 * h0c1 + b1 * h0c0;
                C2 = b1 * h0c1 + b2 * h0c0; C3 = b2 * h0c1;
            }
        } else {
            C0 = h0c0; C1 = h0c1; C2 = 0.f; C3 = 0.f;
        }
        const float* __restrict__ W = g_taps[s >> 1];
        float w0 = W[tid];
        float w1 = (tid >= 1) ? W[tid - 1] : 0.f;
        float w2 = (tid >= 2) ? W[tid - 2] : 0.f;
        float w3 = (tid >= 3) ? W[tid - 3] : 0.f;
        taps[tid] = C0 * w0 + C1 * w1 + C2 * w2 + C3 * w3;
    }
    __syncthreads();

    float a0 = 0.f, a1 = 0.f, a2 = 0.f;
    const float* e0 = &est[128 + tid];
    #pragma unroll 4
    for (int j = 0; j < w; ++j) {
        float h = taps[j];
        a0 += h * e0[-j];
        a1 += h * e0[128 - j];
        a2 += h * e0[256 - j];
    }

    const int sup = w + 255;            // conv support length
    float* __restrict__ row = out + (size_t)(z * BATCH + b) * T;
    const int t0 = off + tid;
    if (tid       < sup && t0       < T) atomicAdd(&row[t0],       a0);
    if (tid + 128 < sup && t0 + 128 < T) atomicAdd(&row[t0 + 128], a1);
    if (tid + 256 < sup && t0 + 256 < T) atomicAdd(&row[t0 + 256], a2);
}

extern "C" void kernel_launch(void* const* d_in, const int* in_sizes, int n_in,
                              void* d_out, int out_size)
{
    const int*   lengthp = (const int*)  d_in[0];
    const float* pluckp  = (const float*)d_in[1];
    const float* exc     = (const float*)d_in[2];
    const float* ngp     = (const float*)d_in[3];
    const float* bgp     = (const float*)d_in[4];
    float* out = (float*)d_out;

    const int T  = in_sizes[2] / BATCH;          // excitation is (8, T)
    const int n4 = out_size / 4;
    const int nfill = (n4 + FILLPB - 1) / FILLPB;

    rows_and_fill<<<NROWBLK + nfill, NTW>>>(lengthp, pluckp, ngp, bgp, out, n4, T);
    apply_window<<<2 * BATCH * SMAX, NTW>>>(lengthp, pluckp, ngp, bgp, exc, out, T);
}

// round 14
// speedup vs baseline: 1.5541x; 1.0419x over previous
#include <cuda_runtime.h>
#include <math.h>

#define BATCH    8
#define TAPS     128    // row width 3k+1 <= 121 for k <= 40; +3 C-conv <= 124
#define NROWBLK  41     // rows k = 0..40  (n_steps <= 80)
#define SMAX     81     // windows s = 0..80
#define NTW      128
#define FILLPB   512    // float4 per fill block (128 thr x 4)

// Operator powers W_k = M^k. Row k serves steps 2k and 2k+1.
__device__ float g_taps[NROWBLK][TAPS];

// ---------------------------------------------------------------------------
// Kernel 1: blocks 0..40 each build one row W_k = M^k by per-block repeated
// squaring (squarings P->P*P, one product-conv per set bit of k; <= 7
// barrier-separated convs). Blocks >= NROWBLK zero the output buffer.
// M = A conv B is chain-independent (conv of fixed FIRs commutes).
// ---------------------------------------------------------------------------
__global__ void __launch_bounds__(NTW)
rows_and_fill(const int* __restrict__ lengthp,
              const float* __restrict__ pluckp,
              const float* __restrict__ ngp,
              const float* __restrict__ bgp,
              float* __restrict__ out, int n4, int T)
{
    const int tid = threadIdx.x;

    if (blockIdx.x >= NROWBLK) {
        const int base = (blockIdx.x - NROWBLK) * FILLPB + tid;
        const float4 z4 = make_float4(0.f, 0.f, 0.f, 0.f);
        #pragma unroll
        for (int i = 0; i < 4; ++i) {
            int idx = base + i * NTW;
            if (idx < n4) ((float4*)out)[idx] = z4;
        }
        return;
    }

    const int k = blockIdx.x;           // row index (block-uniform)
    const int length = lengthp[0];
    int n_steps = T / length;
    if (n_steps > 80) n_steps = 80;
    if (k > (n_steps >> 1)) return;     // unused row: uniform exit

    // M = A conv B
    const float p  = pluckp[0];
    const float ng = ngp[0];
    const float bg = bgp[0];
    const float stringL = (float)length - 0.11f;
    const float dU2 = 2.0f * (stringL * p);
    const float dD2 = 2.0f * (stringL * (1.0f - p));
    const float f1 = dU2 - floorf(dU2);
    const float f2 = dD2 - floorf(dD2);
    const float bscale = (-bg) * 0.5f;
    const float a0 = -ng * (1.0f - f1), a1 = -ng * f1;
    const float b0 = bscale * (1.0f - f2), b1 = bscale, b2 = bscale * f2;
    const float m0 = a0 * b0;
    const float m1 = a0 * b1 + a1 * b0;
    const float m2 = a0 * b2 + a1 * b1;
    const float m3 = a1 * b2;

    // Buffers left-padded with 128 zeros: tap t at buf[128+t].
    __shared__ float bufA[256], bufB[256], bufP[256], bufQ[256];
    bufA[tid] = 0.f; bufA[128 + tid] = 0.f;
    bufB[tid] = 0.f; bufB[128 + tid] = 0.f;
    bufP[tid] = 0.f; bufP[128 + tid] = 0.f;
    bufQ[tid] = 0.f; bufQ[128 + tid] = 0.f;
    __syncthreads();
    if (tid == 0) {
        bufA[128] = 1.0f;               // cur = delta
        bufP[128] = m0; bufP[129] = m1; bufP[130] = m2; bufP[131] = m3;
    }
    __syncthreads();

    float *cur = bufA, *curN = bufB, *Pc = bufP, *Pn = bufQ;
    int rem = k;
    int lenP = 4;                       // width of P = M^(2^j): 4,7,13,25,49,97
    while (rem) {
        if (rem & 1) {                  // cur = cur (*) P
            float acc = 0.f;
            const float* pc = Pc + 128;
            const float* cu = cur + 128 + tid;
            for (int d = 0; d < lenP; ++d) acc += pc[d] * cu[-d];
            curN[128 + tid] = acc;      // distinct buffer: no read/write race
            float* t = cur; cur = curN; curN = t;
            __syncthreads();
        }
        rem >>= 1;
        if (rem) {                      // P = P (*) P
            float acc = 0.f;
            const float* pc = Pc + 128;
            for (int d = 0; d < lenP; ++d) acc += pc[d] * pc[tid - d];
            Pn[128 + tid] = acc;
            float* t = Pc; Pc = Pn; Pn = t;
            lenP = 2 * lenP - 1;
            __syncthreads();
        }
    }

    g_taps[k][tid] = cur[128 + tid];
}

// ---------------------------------------------------------------------------
// Kernel 2: one block per window (z, b, s). h_s = C (*) W_{s>>1} (<=4 coeff)
// built into smem, then conv with the excitation burst.
// Layout: 3 CONSECUTIVE outputs per thread (t0 = off + 3*tid; stride 3 is
// coprime with 32 banks -> conflict-free). A 3x3 j-group touches only 5
// contiguous est values -> 8 LDS + 9 FMA per group. Tail via zero-padded
// taps (rows are zero beyond their width). Any output address is covered by
// <= 2 windows (s->s+2 spacing ~ 2*stringL > 2*379), so 2-operand fp
// atomicAdd onto a zeroed buffer is order-independent -> deterministic.
// ---------------------------------------------------------------------------
__global__ void __launch_bounds__(NTW)
apply_window(const int* __restrict__ lengthp,
             const float* __restrict__ pluckp,
             const float* __restrict__ ngp,
             const float* __restrict__ bgp,
             const float* __restrict__ exc,
             float* __restrict__ out, int T)
{
    const int blk = blockIdx.x;
    const int s   = blk % SMAX;
    const int rb  = blk / SMAX;         // 0..15
    const int z   = rb >> 3;            // 0 = sl rows, 1 = sr rows
    const int b   = rb & 7;
    const int tid = threadIdx.x;

    const int length = lengthp[0];
    int n_steps = T / length;
    if (n_steps > 80) n_steps = 80;
    if (s > n_steps) return;            // surplus window: block-uniform exit

    const float p      = pluckp[0];
    const float stringL = (float)length - 0.11f;
    const float nUp     = stringL * p;
    const float nDown   = stringL * (1.0f - p);
    const int iU = (int)floorf(nUp);
    const int iD = (int)floorf(nDown);
    const float dU2 = 2.0f * nUp;   const float f1 = dU2 - floorf(dU2);
    const float dD2 = 2.0f * nDown; const float f2 = dD2 - floorf(dD2);
    const int i1 = (int)dU2;
    const int i2 = (int)dD2;

    const int ci = (s & 1) ^ z;
    const int ha = (s + 1) >> 1, hb = s >> 1;
    int off, w;
    if (ci == 0) { off = iU + ha * i1 + hb * i2; w = 2 + ha + 2 * hb; }
    else         { off = iD + ha * i2 + hb * i1; w = 2 + 2 * ha + hb; }
    if (w > 124) w = 124;               // true max 122; taps zero beyond width
    if (off >= T) return;               // window beyond buffer: uniform exit

    __shared__ float est[512];          // est[128 + e], e in [-128, 384); zero-padded
    __shared__ float taps[TAPS];

    est[tid] = 0.f;                     // e in [-128, 0)
    est[384 + tid] = 0.f;               // e in [256, 384)
    {
        const float* __restrict__ x = exc + (size_t)b * T;
        const int ne = min(256, T);     // excitation support is [0,256)
        est[128 + tid]       = (tid       < ne) ? x[tid]       : 0.f;
        est[128 + 128 + tid] = (tid + 128 < ne) ? x[tid + 128] : 0.f;
    }

    // taps = C (*) W_{s>>1}; C <= 4 coeffs (h0 even s, X (*) h0 odd s).
    // W rows are zero beyond their width -> taps zero for j >= w.
    {
        const float fU = nUp   - floorf(nUp);
        const float fD = nDown - floorf(nDown);
        const float fr = ci ? fD : fU;
        const float h0c0 = (1.0f - fr) * 0.5f;
        const float h0c1 = fr * 0.5f;
        float C0, C1, C2, C3;
        if (s & 1) {
            if (ci == 0) {              // A (*) h0
                const float ng = ngp[0];
                const float a0 = -ng * (1.0f - f1), a1 = -ng * f1;
                C0 = a0 * h0c0; C1 = a0 * h0c1 + a1 * h0c0; C2 = a1 * h0c1; C3 = 0.f;
            } else {                    // B (*) h0
                const float bg = bgp[0];
                const float bs = (-bg) * 0.5f;
                const float b0 = bs * (1.0f - f2), b1 = bs, b2 = bs * f2;
                C0 = b0 * h0c0; C1 = b0 * h0c1 + b1 * h0c0;
                C2 = b1 * h0c1 + b2 * h0c0; C3 = b2 * h0c1;
            }
        } else {
            C0 = h0c0; C1 = h0c1; C2 = 0.f; C3 = 0.f;
        }
        const float* __restrict__ W = g_taps[s >> 1];
        float w0 = W[tid];
        float w1 = (tid >= 1) ? W[tid - 1] : 0.f;
        float w2 = (tid >= 2) ? W[tid - 2] : 0.f;
        float w3 = (tid >= 3) ? W[tid - 3] : 0.f;
        taps[tid] = C0 * w0 + C1 * w1 + C2 * w2 + C3 * w3;
    }
    __syncthreads();

    // 3 consecutive outputs per thread; j in groups of 3 sharing 5 est loads.
    float a0 = 0.f, a1 = 0.f, a2 = 0.f;
    const int w3 = ((w + 2) / 3) * 3;   // <= 126; taps[j] == 0 for j >= w
    const float* pp = &est[128 + 3 * tid];
    #pragma unroll 2
    for (int j = 0; j < w3; j += 3) {
        const float h0 = taps[j], h1 = taps[j + 1], h2 = taps[j + 2];
        const float em2 = pp[-2], em1 = pp[-1], e0v = pp[0];
        const float e1  = pp[1],  e2  = pp[2];
        a0 += h0 * e0v + h1 * em1 + h2 * em2;
        a1 += h0 * e1  + h1 * e0v + h2 * em1;
        a2 += h0 * e2  + h1 * e1  + h2 * e0v;
        pp -= 3;
    }

    const int sup = w + 255;            // conv support length (<= 379)
    float* __restrict__ row = out + (size_t)(z * BATCH + b) * T;
    const int o0 = 3 * tid;
    const int t0 = off + o0;
    if (o0     < sup && t0     < T) atomicAdd(&row[t0],     a0);
    if (o0 + 1 < sup && t0 + 1 < T) atomicAdd(&row[t0 + 1], a1);
    if (o0 + 2 < sup && t0 + 2 < T) atomicAdd(&row[t0 + 2], a2);
}

extern "C" void kernel_launch(void* const* d_in, const int* in_sizes, int n_in,
                              void* d_out, int out_size)
{
    const int*   lengthp = (const int*)  d_in[0];
    const float* pluckp  = (const float*)d_in[1];
    const float* exc     = (const float*)d_in[2];
    const float* ngp     = (const float*)d_in[3];
    const float* bgp     = (const float*)d_in[4];
    float* out = (float*)d_out;

    const int T  = in_sizes[2] / BATCH;          // excitation is (8, T)
    const int n4 = out_size / 4;
    const int nfill = (n4 + FILLPB - 1) / FILLPB;

    rows_and_fill<<<NROWBLK + nfill, NTW>>>(lengthp, pluckp, ngp, bgp, out, n4, T);
    apply_window<<<2 * BATCH * SMAX, NTW>>>(lengthp, pluckp, ngp, bgp, exc, out, T);
}

// round 15
// speedup vs baseline: 1.5610x; 1.0044x over previous
#include <cuda_runtime.h>
#include <math.h>

#define BATCH    8
#define TAPS     128    // row width 3k+1 <= 121 for k <= 40; +3 C-conv <= 124
#define NROWBLK  41     // rows k = 0..40  (n_steps <= 80)
#define SMAX     81     // windows s = 0..80
#define NTW      128
#define FILLPB   512    // float4 per fill block (128 thr x 4)

// Operator powers W_k = M^k. Row k serves steps 2k and 2k+1.
__device__ float g_taps[NROWBLK][TAPS];

// ---------------------------------------------------------------------------
// Kernel 1 (verbatim, R12-verified): blocks 0..40 build row W_k = M^k by
// per-block repeated squaring; blocks >= NROWBLK zero the output buffer.
// ---------------------------------------------------------------------------
__global__ void __launch_bounds__(NTW)
rows_and_fill(const int* __restrict__ lengthp,
              const float* __restrict__ pluckp,
              const float* __restrict__ ngp,
              const float* __restrict__ bgp,
              float* __restrict__ out, int n4, int T)
{
    const int tid = threadIdx.x;

    if (blockIdx.x >= NROWBLK) {
        const int base = (blockIdx.x - NROWBLK) * FILLPB + tid;
        const float4 z4 = make_float4(0.f, 0.f, 0.f, 0.f);
        #pragma unroll
        for (int i = 0; i < 4; ++i) {
            int idx = base + i * NTW;
            if (idx < n4) ((float4*)out)[idx] = z4;
        }
        return;
    }

    const int k = blockIdx.x;
    const int length = lengthp[0];
    int n_steps = T / length;
    if (n_steps > 80) n_steps = 80;
    if (k > (n_steps >> 1)) return;

    const float p  = pluckp[0];
    const float ng = ngp[0];
    const float bg = bgp[0];
    const float stringL = (float)length - 0.11f;
    const float dU2 = 2.0f * (stringL * p);
    const float dD2 = 2.0f * (stringL * (1.0f - p));
    const float f1 = dU2 - floorf(dU2);
    const float f2 = dD2 - floorf(dD2);
    const float bscale = (-bg) * 0.5f;
    const float a0 = -ng * (1.0f - f1), a1 = -ng * f1;
    const float b0 = bscale * (1.0f - f2), b1 = bscale, b2 = bscale * f2;
    const float m0 = a0 * b0;
    const float m1 = a0 * b1 + a1 * b0;
    const float m2 = a0 * b2 + a1 * b1;
    const float m3 = a1 * b2;

    __shared__ float bufA[256], bufB[256], bufP[256], bufQ[256];
    bufA[tid] = 0.f; bufA[128 + tid] = 0.f;
    bufB[tid] = 0.f; bufB[128 + tid] = 0.f;
    bufP[tid] = 0.f; bufP[128 + tid] = 0.f;
    bufQ[tid] = 0.f; bufQ[128 + tid] = 0.f;
    __syncthreads();
    if (tid == 0) {
        bufA[128] = 1.0f;               // cur = delta
        bufP[128] = m0; bufP[129] = m1; bufP[130] = m2; bufP[131] = m3;
    }
    __syncthreads();

    float *cur = bufA, *curN = bufB, *Pc = bufP, *Pn = bufQ;
    int rem = k;
    int lenP = 4;
    while (rem) {
        if (rem & 1) {
            float acc = 0.f;
            const float* pc = Pc + 128;
            const float* cu = cur + 128 + tid;
            for (int d = 0; d < lenP; ++d) acc += pc[d] * cu[-d];
            curN[128 + tid] = acc;
            float* t = cur; cur = curN; curN = t;
            __syncthreads();
        }
        rem >>= 1;
        if (rem) {
            float acc = 0.f;
            const float* pc = Pc + 128;
            for (int d = 0; d < lenP; ++d) acc += pc[d] * pc[tid - d];
            Pn[128 + tid] = acc;
            float* t = Pc; Pc = Pn; Pn = t;
            lenP = 2 * lenP - 1;
            __syncthreads();
        }
    }

    g_taps[k][tid] = cur[128 + tid];
}

// ---------------------------------------------------------------------------
// Kernel 2: one block per (b, s) — the z=0 and z=1 windows share the SAME
// tap row W_{s>>1} and the SAME excitation; they differ only in the <=4-coeff
// C filter and output offset. Fusing the pair amortizes est/param/barrier
// cost 2x and shares the 5 est LDS per 3-j group across 18 MACs.
// 3 consecutive outputs per thread per z; taps arrays zero beyond widths so
// one uniform loop to max(w0,w1) is exact. <=2 windows cover any output
// address -> 2-operand fp atomicAdd onto zeroed buffer is deterministic.
// ---------------------------------------------------------------------------
__global__ void __launch_bounds__(NTW)
apply_window(const int* __restrict__ lengthp,
             const float* __restrict__ pluckp,
             const float* __restrict__ ngp,
             const float* __restrict__ bgp,
             const float* __restrict__ exc,
             float* __restrict__ out, int T)
{
    const int blk = blockIdx.x;
    const int s   = blk % SMAX;
    const int b   = blk / SMAX;         // 0..7
    const int tid = threadIdx.x;

    const int length = lengthp[0];
    int n_steps = T / length;
    if (n_steps > 80) n_steps = 80;
    if (s > n_steps) return;            // surplus window: block-uniform exit

    const float p      = pluckp[0];
    const float stringL = (float)length - 0.11f;
    const float nUp     = stringL * p;
    const float nDown   = stringL * (1.0f - p);
    const int iU = (int)floorf(nUp);
    const int iD = (int)floorf(nDown);
    const float dU2 = 2.0f * nUp;   const float f1 = dU2 - floorf(dU2);
    const float dD2 = 2.0f * nDown; const float f2 = dD2 - floorf(dD2);
    const int i1 = (int)dU2;
    const int i2 = (int)dD2;

    const int parity = s & 1;
    const int ha = (s + 1) >> 1, hb = s >> 1;
    // geometry for ci = 0 and ci = 1
    const int offc0 = iU + ha * i1 + hb * i2;  int wc0 = 2 + ha + 2 * hb;
    const int offc1 = iD + ha * i2 + hb * i1;  int wc1 = 2 + 2 * ha + hb;
    if (wc0 > 124) wc0 = 124;
    if (wc1 > 124) wc1 = 124;
    // z=0 uses ci0 = parity, z=1 uses ci1 = 1 - parity
    const int off0 = parity ? offc1 : offc0;  const int w0 = parity ? wc1 : wc0;
    const int off1 = parity ? offc0 : offc1;  const int w1 = parity ? wc0 : wc1;
    if (off0 >= T && off1 >= T) return; // both beyond buffer: uniform exit

    __shared__ float est[512];          // est[128 + e], e in [-128, 384); zero-padded
    __shared__ float taps0[TAPS], taps1[TAPS];

    est[tid] = 0.f;                     // e in [-128, 0)
    est[384 + tid] = 0.f;               // e in [256, 384)
    {
        const float* __restrict__ x = exc + (size_t)b * T;
        const int ne = min(256, T);     // excitation support is [0,256)
        est[128 + tid]       = (tid       < ne) ? x[tid]       : 0.f;
        est[128 + 128 + tid] = (tid + 128 < ne) ? x[tid + 128] : 0.f;
    }

    // Build BOTH C filters (ci = 0 and ci = 1), apply to shared W row.
    {
        const float fU = nUp   - floorf(nUp);
        const float fD = nDown - floorf(nDown);
        const float ng = ngp[0];
        const float bg = bgp[0];
        const float bs = (-bg) * 0.5f;
        const float a0 = -ng * (1.0f - f1), a1 = -ng * f1;
        const float b0 = bs * (1.0f - f2), b1 = bs, b2 = bs * f2;

        // ci = 0 coefficients
        const float u00 = (1.0f - fU) * 0.5f, u01 = fU * 0.5f;
        float Cc0_0, Cc0_1, Cc0_2, Cc0_3;
        if (parity) {                   // odd s: A (*) h0
            Cc0_0 = a0 * u00; Cc0_1 = a0 * u01 + a1 * u00; Cc0_2 = a1 * u01; Cc0_3 = 0.f;
        } else {
            Cc0_0 = u00; Cc0_1 = u01; Cc0_2 = 0.f; Cc0_3 = 0.f;
        }
        // ci = 1 coefficients
        const float d00 = (1.0f - fD) * 0.5f, d01 = fD * 0.5f;
        float Cc1_0, Cc1_1, Cc1_2, Cc1_3;
        if (parity) {                   // odd s: B (*) h0
            Cc1_0 = b0 * d00; Cc1_1 = b0 * d01 + b1 * d00;
            Cc1_2 = b1 * d01 + b2 * d00; Cc1_3 = b2 * d01;
        } else {
            Cc1_0 = d00; Cc1_1 = d01; Cc1_2 = 0.f; Cc1_3 = 0.f;
        }

        const float* __restrict__ W = g_taps[s >> 1];
        float w0v = W[tid];
        float w1v = (tid >= 1) ? W[tid - 1] : 0.f;
        float w2v = (tid >= 2) ? W[tid - 2] : 0.f;
        float w3v = (tid >= 3) ? W[tid - 3] : 0.f;
        const float tc0 = Cc0_0 * w0v + Cc0_1 * w1v + Cc0_2 * w2v + Cc0_3 * w3v;
        const float tc1 = Cc1_0 * w0v + Cc1_1 * w1v + Cc1_2 * w2v + Cc1_3 * w3v;
        // taps0 = z=0's filter (ci = parity), taps1 = z=1's (ci = 1-parity)
        taps0[tid] = parity ? tc1 : tc0;
        taps1[tid] = parity ? tc0 : tc1;
    }
    __syncthreads();

    // Fused conv: 5 est LDS per 3-j group feed both z accumulator triples.
    float A0 = 0.f, A1 = 0.f, A2 = 0.f;   // z = 0
    float B0 = 0.f, B1 = 0.f, B2 = 0.f;   // z = 1
    const int wm = (w0 > w1) ? w0 : w1;
    const int w3 = ((wm + 2) / 3) * 3;    // <= 126; taps zero beyond widths
    const float* pp = &est[128 + 3 * tid];
    #pragma unroll 2
    for (int j = 0; j < w3; j += 3) {
        const float h00 = taps0[j], h01 = taps0[j + 1], h02 = taps0[j + 2];
        const float h10 = taps1[j], h11 = taps1[j + 1], h12 = taps1[j + 2];
        const float em2 = pp[-2], em1 = pp[-1], e0v = pp[0];
        const float e1  = pp[1],  e2  = pp[2];
        A0 += h00 * e0v + h01 * em1 + h02 * em2;
        A1 += h00 * e1  + h01 * e0v + h02 * em1;
        A2 += h00 * e2  + h01 * e1  + h02 * e0v;
        B0 += h10 * e0v + h11 * em1 + h12 * em2;
        B1 += h10 * e1  + h11 * e0v + h12 * em1;
        B2 += h10 * e2  + h11 * e1  + h12 * e0v;
        pp -= 3;
    }

    const int o0 = 3 * tid;
    {
        const int sup0 = w0 + 255;
        float* __restrict__ row = out + (size_t)b * T;           // sl row
        const int t0 = off0 + o0;
        if (o0     < sup0 && t0     < T) atomicAdd(&row[t0],     A0);
        if (o0 + 1 < sup0 && t0 + 1 < T) atomicAdd(&row[t0 + 1], A1);
        if (o0 + 2 < sup0 && t0 + 2 < T) atomicAdd(&row[t0 + 2], A2);
    }
    {
        const int sup1 = w1 + 255;
        float* __restrict__ row = out + (size_t)(BATCH + b) * T; // sr row
        const int t0 = off1 + o0;
        if (o0     < sup1 && t0     < T) atomicAdd(&row[t0],     B0);
        if (o0 + 1 < sup1 && t0 + 1 < T) atomicAdd(&row[t0 + 1], B1);
        if (o0 + 2 < sup1 && t0 + 2 < T) atomicAdd(&row[t0 + 2], B2);
    }
}

extern "C" void kernel_launch(void* const* d_in, const int* in_sizes, int n_in,
                              void* d_out, int out_size)
{
    const int*   lengthp = (const int*)  d_in[0];
    const float* pluckp  = (const float*)d_in[1];
    const float* exc     = (const float*)d_in[2];
    const float* ngp     = (const float*)d_in[3];
    const float* bgp     = (const float*)d_in[4];
    float* out = (float*)d_out;

    const int T  = in_sizes[2] / BATCH;          // excitation is (8, T)
    const int n4 = out_size / 4;
    const int nfill = (n4 + FILLPB - 1) / FILLPB;

    rows_and_fill<<<NROWBLK + nfill, NTW>>>(lengthp, pluckp, ngp, bgp, out, n4, T);
    apply_window<<<BATCH * SMAX, NTW>>>(lengthp, pluckp, ngp, bgp, exc, out, T);
}

// round 16
// speedup vs baseline: 1.7340x; 1.1108x over previous
#include <cuda_runtime.h>
#include <math.h>
#include <stdint.h>

#define BATCH    8
#define TAPS     128    // row width 3k+1 <= 121 for k <= 40; +3 C-conv <= 124
#define NROWBLK  41     // rows k = 0..40  (n_steps <= 80)
#define SMAX     81     // windows s = 0..80
#define NTW      128
#define FILLPB   512    // float4 per fill block (128 thr x 4)

// Packed f32x2 helpers (PTX ISA 8.6, sm_100+). Lanes are independent fp32
// FMAs -> bitwise identical to scalar FFMA per lane.
#define PK2(out, v)  asm("mov.b64 %0, {%1, %1};" : "=l"(out) : "f"(v))
#define FMA2(acc, a, b) \
    asm("fma.rn.f32x2 %0, %1, %2, %0;" : "+l"(acc) : "l"(a), "l"(b))
#define UNPK2(lo, hi, v) \
    asm("mov.b64 {%0, %1}, %2;" : "=f"(lo), "=f"(hi) : "l"(v))

// Operator powers W_k = M^k. Row k serves steps 2k and 2k+1.
__device__ float g_taps[NROWBLK][TAPS];

// ---------------------------------------------------------------------------
// Kernel 1: blocks 0..40 build row W_k = M^k by per-block repeated squaring;
// blocks >= NROWBLK zero the output buffer. Conv loops use 4 partial
// accumulators to cut the serial FMA-chain depth 4x.
// ---------------------------------------------------------------------------
__global__ void __launch_bounds__(NTW)
rows_and_fill(const int* __restrict__ lengthp,
              const float* __restrict__ pluckp,
              const float* __restrict__ ngp,
              const float* __restrict__ bgp,
              float* __restrict__ out, int n4, int T)
{
    const int tid = threadIdx.x;

    if (blockIdx.x >= NROWBLK) {
        const int base = (blockIdx.x - NROWBLK) * FILLPB + tid;
        const float4 z4 = make_float4(0.f, 0.f, 0.f, 0.f);
        #pragma unroll
        for (int i = 0; i < 4; ++i) {
            int idx = base + i * NTW;
            if (idx < n4) ((float4*)out)[idx] = z4;
        }
        return;
    }

    const int k = blockIdx.x;
    const int length = lengthp[0];
    int n_steps = T / length;
    if (n_steps > 80) n_steps = 80;
    if (k > (n_steps >> 1)) return;

    const float p  = pluckp[0];
    const float ng = ngp[0];
    const float bg = bgp[0];
    const float stringL = (float)length - 0.11f;
    const float dU2 = 2.0f * (stringL * p);
    const float dD2 = 2.0f * (stringL * (1.0f - p));
    const float f1 = dU2 - floorf(dU2);
    const float f2 = dD2 - floorf(dD2);
    const float bscale = (-bg) * 0.5f;
    const float a0 = -ng * (1.0f - f1), a1 = -ng * f1;
    const float b0 = bscale * (1.0f - f2), b1 = bscale, b2 = bscale * f2;
    const float m0 = a0 * b0;
    const float m1 = a0 * b1 + a1 * b0;
    const float m2 = a0 * b2 + a1 * b1;
    const float m3 = a1 * b2;

    __shared__ float bufA[256], bufB[256], bufP[256], bufQ[256];
    bufA[tid] = 0.f; bufA[128 + tid] = 0.f;
    bufB[tid] = 0.f; bufB[128 + tid] = 0.f;
    bufP[tid] = 0.f; bufP[128 + tid] = 0.f;
    bufQ[tid] = 0.f; bufQ[128 + tid] = 0.f;
    __syncthreads();
    if (tid == 0) {
        bufA[128] = 1.0f;               // cur = delta
        bufP[128] = m0; bufP[129] = m1; bufP[130] = m2; bufP[131] = m3;
    }
    __syncthreads();

    float *cur = bufA, *curN = bufB, *Pc = bufP, *Pn = bufQ;
    int rem = k;
    int lenP = 4;                       // width of P = M^(2^j): 4,7,13,25,49,97
    while (rem) {
        if (rem & 1) {                  // cur = cur (*) P
            float s0 = 0.f, s1 = 0.f, s2 = 0.f, s3 = 0.f;
            const float* pc = Pc + 128;
            const float* cu = cur + 128 + tid;
            int d = 0;
            for (; d + 3 < lenP; d += 4) {
                s0 += pc[d]     * cu[-d];
                s1 += pc[d + 1] * cu[-d - 1];
                s2 += pc[d + 2] * cu[-d - 2];
                s3 += pc[d + 3] * cu[-d - 3];
            }
            for (; d < lenP; ++d) s0 += pc[d] * cu[-d];
            curN[128 + tid] = (s0 + s1) + (s2 + s3);
            float* t = cur; cur = curN; curN = t;
            __syncthreads();
        }
        rem >>= 1;
        if (rem) {                      // P = P (*) P
            float s0 = 0.f, s1 = 0.f, s2 = 0.f, s3 = 0.f;
            const float* pc = Pc + 128;
            int d = 0;
            for (; d + 3 < lenP; d += 4) {
                s0 += pc[d]     * pc[tid - d];
                s1 += pc[d + 1] * pc[tid - d - 1];
                s2 += pc[d + 2] * pc[tid - d - 2];
                s3 += pc[d + 3] * pc[tid - d - 3];
            }
            for (; d < lenP; ++d) s0 += pc[d] * pc[tid - d];
            Pn[128 + tid] = (s0 + s1) + (s2 + s3);
            float* t = Pc; Pc = Pn; Pn = t;
            lenP = 2 * lenP - 1;
            __syncthreads();
        }
    }

    g_taps[k][tid] = cur[128 + tid];
}

// ---------------------------------------------------------------------------
// Kernel 2: one block per (b, s); z=0/z=1 windows share the tap row and the
// excitation. Taps stored interleaved (float2) so each (z0,z1) pair is one
// LDS.64; MACs run as packed fma.rn.f32x2 (9 FFMA2 per 3-j group instead of
// 18 FFMA); est values live in pre-broadcast packed registers rotated across
// groups (3 new LDS + 3 packs per group instead of 5 LDS). Warps entirely
// above supm skip the loop (warp-uniform guard). <=2 windows cover any
// output address -> atomicAdd onto zeroed buffer is deterministic.
// ---------------------------------------------------------------------------
__global__ void __launch_bounds__(NTW)
apply_window(const int* __restrict__ lengthp,
             const float* __restrict__ pluckp,
             const float* __restrict__ ngp,
             const float* __restrict__ bgp,
             const float* __restrict__ exc,
             float* __restrict__ out, int T)
{
    const int blk = blockIdx.x;
    const int s   = blk % SMAX;
    const int b   = blk / SMAX;         // 0..7
    const int tid = threadIdx.x;

    const int length = lengthp[0];
    int n_steps = T / length;
    if (n_steps > 80) n_steps = 80;
    if (s > n_steps) return;            // surplus window: block-uniform exit

    const float p      = pluckp[0];
    const float stringL = (float)length - 0.11f;
    const float nUp     = stringL * p;
    const float nDown   = stringL * (1.0f - p);
    const int iU = (int)floorf(nUp);
    const int iD = (int)floorf(nDown);
    const float dU2 = 2.0f * nUp;   const float f1 = dU2 - floorf(dU2);
    const float dD2 = 2.0f * nDown; const float f2 = dD2 - floorf(dD2);
    const int i1 = (int)dU2;
    const int i2 = (int)dD2;

    const int parity = s & 1;
    const int ha = (s + 1) >> 1, hb = s >> 1;
    const int offc0 = iU + ha * i1 + hb * i2;  int wc0 = 2 + ha + 2 * hb;
    const int offc1 = iD + ha * i2 + hb * i1;  int wc1 = 2 + 2 * ha + hb;
    if (wc0 > 124) wc0 = 124;
    if (wc1 > 124) wc1 = 124;
    const int off0 = parity ? offc1 : offc0;  const int w0 = parity ? wc1 : wc0;
    const int off1 = parity ? offc0 : offc1;  const int w1 = parity ? wc0 : wc1;
    if (off0 >= T && off1 >= T) return;

    // est layout: sample e at est[134 + e], e in [-134, 386); zero-padded.
    __shared__ float est[520];
    __shared__ float2 taps01[TAPS];     // .x = z=0 filter, .y = z=1 filter

    est[tid] = 0.f;                     // [0,128)
    if (tid < 6)  est[128 + tid] = 0.f; // [128,134)
    est[390 + tid] = 0.f;               // [390,518)
    if (tid < 2)  est[518 + tid] = 0.f; // [518,520)
    {
        const float* __restrict__ x = exc + (size_t)b * T;
        const int ne = min(256, T);     // excitation support is [0,256)
        est[134 + tid]       = (tid       < ne) ? x[tid]       : 0.f;
        est[134 + 128 + tid] = (tid + 128 < ne) ? x[tid + 128] : 0.f;
    }

    // Build both C filters, apply to the shared W row, store interleaved.
    {
        const float fU = nUp   - floorf(nUp);
        const float fD = nDown - floorf(nDown);
        const float ng = ngp[0];
        const float bg = bgp[0];
        const float bs = (-bg) * 0.5f;
        const float a0 = -ng * (1.0f - f1), a1 = -ng * f1;
        const float b0 = bs * (1.0f - f2), b1 = bs, b2 = bs * f2;

        const float u00 = (1.0f - fU) * 0.5f, u01 = fU * 0.5f;
        float Cc0_0, Cc0_1, Cc0_2, Cc0_3;
        if (parity) {                   // odd s: A (*) h0
            Cc0_0 = a0 * u00; Cc0_1 = a0 * u01 + a1 * u00; Cc0_2 = a1 * u01; Cc0_3 = 0.f;
        } else {
            Cc0_0 = u00; Cc0_1 = u01; Cc0_2 = 0.f; Cc0_3 = 0.f;
        }
        const float d00 = (1.0f - fD) * 0.5f, d01 = fD * 0.5f;
        float Cc1_0, Cc1_1, Cc1_2, Cc1_3;
        if (parity) {                   // odd s: B (*) h0
            Cc1_0 = b0 * d00; Cc1_1 = b0 * d01 + b1 * d00;
            Cc1_2 = b1 * d01 + b2 * d00; Cc1_3 = b2 * d01;
        } else {
            Cc1_0 = d00; Cc1_1 = d01; Cc1_2 = 0.f; Cc1_3 = 0.f;
        }

        const float* __restrict__ W = g_taps[s >> 1];
        float w0v = W[tid];
        float w1v = (tid >= 1) ? W[tid - 1] : 0.f;
        float w2v = (tid >= 2) ? W[tid - 2] : 0.f;
        float w3v = (tid >= 3) ? W[tid - 3] : 0.f;
        const float tc0 = Cc0_0 * w0v + Cc0_1 * w1v + Cc0_2 * w2v + Cc0_3 * w3v;
        const float tc1 = Cc1_0 * w0v + Cc1_1 * w1v + Cc1_2 * w2v + Cc1_3 * w3v;
        taps01[tid] = parity ? make_float2(tc1, tc0) : make_float2(tc0, tc1);
    }
    __syncthreads();

    const int wm   = (w0 > w1) ? w0 : w1;
    const int supm = wm + 255;
    const int w3   = ((wm + 2) / 3) * 3;   // <= 126; taps zero beyond widths

    uint64_t AB0 = 0ull, AB1 = 0ull, AB2 = 0ull;  // lo = z0, hi = z1

    if (3 * (tid & ~31) < supm) {       // warp-uniform skip of dead warps
        const float* pp = &est[134 + 3 * tid];
        const uint64_t* __restrict__ tp = (const uint64_t*)taps01;
        uint64_t pem2, pem1, pe0, pe1, pe2;
        PK2(pem2, pp[-2]); PK2(pem1, pp[-1]); PK2(pe0, pp[0]);
        PK2(pe1,  pp[1]);  PK2(pe2,  pp[2]);
        for (int j = 0; j < w3; j += 3) {
            const uint64_t h0 = tp[j], h1 = tp[j + 1], h2 = tp[j + 2];
            FMA2(AB0, h0, pe0); FMA2(AB0, h1, pem1); FMA2(AB0, h2, pem2);
            FMA2(AB1, h0, pe1); FMA2(AB1, h1, pe0);  FMA2(AB1, h2, pem1);
            FMA2(AB2, h0, pe2); FMA2(AB2, h1, pe1);  FMA2(AB2, h2, pe0);
            pe2 = pem1; pe1 = pem2;     // rotate window down by 3
            pp -= 3;                    // prefetch (in-bounds even on last iter)
            PK2(pe0, pp[0]); PK2(pem1, pp[-1]); PK2(pem2, pp[-2]);
        }
    }

    float A0, A1, A2, B0, B1, B2;
    UNPK2(A0, B0, AB0); UNPK2(A1, B1, AB1); UNPK2(A2, B2, AB2);

    const int o0 = 3 * tid;
    {
        const int sup0 = w0 + 255;
        float* __restrict__ row = out + (size_t)b * T;           // sl row
        const int t0 = off0 + o0;
        if (o0     < sup0 && t0     < T) atomicAdd(&row[t0],     A0);
        if (o0 + 1 < sup0 && t0 + 1 < T) atomicAdd(&row[t0 + 1], A1);
        if (o0 + 2 < sup0 && t0 + 2 < T) atomicAdd(&row[t0 + 2], A2);
    }
    {
        const int sup1 = w1 + 255;
        float* __restrict__ row = out + (size_t)(BATCH + b) * T; // sr row
        const int t0 = off1 + o0;
        if (o0     < sup1 && t0     < T) atomicAdd(&row[t0],     B0);
        if (o0 + 1 < sup1 && t0 + 1 < T) atomicAdd(&row[t0 + 1], B1);
        if (o0 + 2 < sup1 && t0 + 2 < T) atomicAdd(&row[t0 + 2], B2);
    }
}

extern "C" void kernel_launch(void* const* d_in, const int* in_sizes, int n_in,
                              void* d_out, int out_size)
{
    const int*   lengthp = (const int*)  d_in[0];
    const float* pluckp  = (const float*)d_in[1];
    const float* exc     = (const float*)d_in[2];
    const float* ngp     = (const float*)d_in[3];
    const float* bgp     = (const float*)d_in[4];
    float* out = (float*)d_out;

    const int T  = in_sizes[2] / BATCH;          // excitation is (8, T)
    const int n4 = out_size / 4;
    const int nfill = (n4 + FILLPB - 1) / FILLPB;

    rows_and_fill<<<NROWBLK + nfill, NTW>>>(lengthp, pluckp, ngp, bgp, out, n4, T);
    apply_window<<<BATCH * SMAX, NTW>>>(lengthp, pluckp, ngp, bgp, exc, out, T);
}

// round 17
// speedup vs baseline: 1.8333x; 1.0573x over previous
#include <cuda_runtime.h>
#include <math.h>
#include <stdint.h>

#define BATCH    8
#define TAPS     128    // row width 3k+1 <= 121 for k <= 40; +3 C-conv <= 124
#define NROWBLK  41     // rows k = 0..40  (n_steps <= 80)
#define SMAX     81     // windows s = 0..80
#define NTW      128
#define FILLPB   512    // float4 per fill block (128 thr x 4)

// Packed f32x2 helpers (PTX ISA 8.6, sm_100+). Lanes are independent fp32
// FMAs -> bitwise identical to scalar FFMA per lane.
#define PK2(out, v)  asm("mov.b64 %0, {%1, %1};" : "=l"(out) : "f"(v))
#define FMA2(acc, a, b) \
    asm("fma.rn.f32x2 %0, %1, %2, %0;" : "+l"(acc) : "l"(a), "l"(b))
#define ADD2(out, a, b) \
    asm("add.rn.f32x2 %0, %1, %2;" : "=l"(out) : "l"(a), "l"(b))
#define UNPK2(lo, hi, v) \
    asm("mov.b64 {%0, %1}, %2;" : "=f"(lo), "=f"(hi) : "l"(v))

// Operator powers W_k = M^k. Row k serves steps 2k and 2k+1.
__device__ float g_taps[NROWBLK][TAPS];

// ---------------------------------------------------------------------------
// Kernel 1 (verbatim, R16-verified): blocks 0..40 build row W_k = M^k by
// per-block repeated squaring (4 partial accumulators cut FMA-chain depth);
// blocks >= NROWBLK zero the output buffer.
// ---------------------------------------------------------------------------
__global__ void __launch_bounds__(NTW)
rows_and_fill(const int* __restrict__ lengthp,
              const float* __restrict__ pluckp,
              const float* __restrict__ ngp,
              const float* __restrict__ bgp,
              float* __restrict__ out, int n4, int T)
{
    const int tid = threadIdx.x;

    if (blockIdx.x >= NROWBLK) {
        const int base = (blockIdx.x - NROWBLK) * FILLPB + tid;
        const float4 z4 = make_float4(0.f, 0.f, 0.f, 0.f);
        #pragma unroll
        for (int i = 0; i < 4; ++i) {
            int idx = base + i * NTW;
            if (idx < n4) ((float4*)out)[idx] = z4;
        }
        return;
    }

    const int k = blockIdx.x;
    const int length = lengthp[0];
    int n_steps = T / length;
    if (n_steps > 80) n_steps = 80;
    if (k > (n_steps >> 1)) return;

    const float p  = pluckp[0];
    const float ng = ngp[0];
    const float bg = bgp[0];
    const float stringL = (float)length - 0.11f;
    const float dU2 = 2.0f * (stringL * p);
    const float dD2 = 2.0f * (stringL * (1.0f - p));
    const float f1 = dU2 - floorf(dU2);
    const float f2 = dD2 - floorf(dD2);
    const float bscale = (-bg) * 0.5f;
    const float a0 = -ng * (1.0f - f1), a1 = -ng * f1;
    const float b0 = bscale * (1.0f - f2), b1 = bscale, b2 = bscale * f2;
    const float m0 = a0 * b0;
    const float m1 = a0 * b1 + a1 * b0;
    const float m2 = a0 * b2 + a1 * b1;
    const float m3 = a1 * b2;

    __shared__ float bufA[256], bufB[256], bufP[256], bufQ[256];
    bufA[tid] = 0.f; bufA[128 + tid] = 0.f;
    bufB[tid] = 0.f; bufB[128 + tid] = 0.f;
    bufP[tid] = 0.f; bufP[128 + tid] = 0.f;
    bufQ[tid] = 0.f; bufQ[128 + tid] = 0.f;
    __syncthreads();
    if (tid == 0) {
        bufA[128] = 1.0f;               // cur = delta
        bufP[128] = m0; bufP[129] = m1; bufP[130] = m2; bufP[131] = m3;
    }
    __syncthreads();

    float *cur = bufA, *curN = bufB, *Pc = bufP, *Pn = bufQ;
    int rem = k;
    int lenP = 4;                       // width of P = M^(2^j): 4,7,13,25,49,97
    while (rem) {
        if (rem & 1) {                  // cur = cur (*) P
            float s0 = 0.f, s1 = 0.f, s2 = 0.f, s3 = 0.f;
            const float* pc = Pc + 128;
            const float* cu = cur + 128 + tid;
            int d = 0;
            for (; d + 3 < lenP; d += 4) {
                s0 += pc[d]     * cu[-d];
                s1 += pc[d + 1] * cu[-d - 1];
                s2 += pc[d + 2] * cu[-d - 2];
                s3 += pc[d + 3] * cu[-d - 3];
            }
            for (; d < lenP; ++d) s0 += pc[d] * cu[-d];
            curN[128 + tid] = (s0 + s1) + (s2 + s3);
            float* t = cur; cur = curN; curN = t;
            __syncthreads();
        }
        rem >>= 1;
        if (rem) {                      // P = P (*) P
            float s0 = 0.f, s1 = 0.f, s2 = 0.f, s3 = 0.f;
            const float* pc = Pc + 128;
            int d = 0;
            for (; d + 3 < lenP; d += 4) {
                s0 += pc[d]     * pc[tid - d];
                s1 += pc[d + 1] * pc[tid - d - 1];
                s2 += pc[d + 2] * pc[tid - d - 2];
                s3 += pc[d + 3] * pc[tid - d - 3];
            }
            for (; d < lenP; ++d) s0 += pc[d] * pc[tid - d];
            Pn[128 + tid] = (s0 + s1) + (s2 + s3);
            float* t = Pc; Pc = Pn; Pn = t;
            lenP = 2 * lenP - 1;
            __syncthreads();
        }
    }

    g_taps[k][tid] = cur[128 + tid];
}

// ---------------------------------------------------------------------------
// Kernel 2: one block per (b, s); z=0/z=1 share the tap row + excitation.
// Interleaved float2 taps, packed fma.rn.f32x2, 3 consecutive outputs per
// thread. NEW: 6 taps per iteration with TWO independent accumulator triples
// (a: j..j+2, b: j+3..j+5) -> chain exposure halves per issued MAC; merged
// with one packed add (partial-sum reassociation, ~1e-7). <=2 windows per
// output address -> atomicAdd onto zeroed buffer is deterministic.
// ---------------------------------------------------------------------------
__global__ void __launch_bounds__(NTW)
apply_window(const int* __restrict__ lengthp,
             const float* __restrict__ pluckp,
             const float* __restrict__ ngp,
             const float* __restrict__ bgp,
             const float* __restrict__ exc,
             float* __restrict__ out, int T)
{
    const int blk = blockIdx.x;
    const int s   = blk % SMAX;
    const int b   = blk / SMAX;         // 0..7
    const int tid = threadIdx.x;

    const int length = lengthp[0];
    int n_steps = T / length;
    if (n_steps > 80) n_steps = 80;
    if (s > n_steps) return;            // surplus window: block-uniform exit

    const float p      = pluckp[0];
    const float stringL = (float)length - 0.11f;
    const float nUp     = stringL * p;
    const float nDown   = stringL * (1.0f - p);
    const int iU = (int)floorf(nUp);
    const int iD = (int)floorf(nDown);
    const float dU2 = 2.0f * nUp;   const float f1 = dU2 - floorf(dU2);
    const float dD2 = 2.0f * nDown; const float f2 = dD2 - floorf(dD2);
    const int i1 = (int)dU2;
    const int i2 = (int)dD2;

    const int parity = s & 1;
    const int ha = (s + 1) >> 1, hb = s >> 1;
    const int offc0 = iU + ha * i1 + hb * i2;  int wc0 = 2 + ha + 2 * hb;
    const int offc1 = iD + ha * i2 + hb * i1;  int wc1 = 2 + 2 * ha + hb;
    if (wc0 > 122) wc0 = 122;
    if (wc1 > 122) wc1 = 122;
    const int off0 = parity ? offc1 : offc0;  const int w0 = parity ? wc1 : wc0;
    const int off1 = parity ? offc0 : offc1;  const int w1 = parity ? wc0 : wc1;
    if (off0 >= T && off1 >= T) return;

    // est layout: sample e at est[134 + e], e in [-134, 386); zero-padded.
    __shared__ float est[520];
    __shared__ float2 taps01[TAPS];     // .x = z=0 filter, .y = z=1 filter

    est[tid] = 0.f;                     // [0,128)
    if (tid < 6)  est[128 + tid] = 0.f; // [128,134)
    est[390 + tid] = 0.f;               // [390,518)
    if (tid < 2)  est[518 + tid] = 0.f; // [518,520)
    {
        const float* __restrict__ x = exc + (size_t)b * T;
        const int ne = min(256, T);     // excitation support is [0,256)
        est[134 + tid]       = (tid       < ne) ? x[tid]       : 0.f;
        est[134 + 128 + tid] = (tid + 128 < ne) ? x[tid + 128] : 0.f;
    }

    // Build both C filters, apply to the shared W row, store interleaved.
    {
        const float fU = nUp   - floorf(nUp);
        const float fD = nDown - floorf(nDown);
        const float ng = ngp[0];
        const float bg = bgp[0];
        const float bs = (-bg) * 0.5f;
        const float a0 = -ng * (1.0f - f1), a1 = -ng * f1;
        const float b0 = bs * (1.0f - f2), b1 = bs, b2 = bs * f2;

        const float u00 = (1.0f - fU) * 0.5f, u01 = fU * 0.5f;
        float Cc0_0, Cc0_1, Cc0_2, Cc0_3;
        if (parity) {                   // odd s: A (*) h0
            Cc0_0 = a0 * u00; Cc0_1 = a0 * u01 + a1 * u00; Cc0_2 = a1 * u01; Cc0_3 = 0.f;
        } else {
            Cc0_0 = u00; Cc0_1 = u01; Cc0_2 = 0.f; Cc0_3 = 0.f;
        }
        const float d00 = (1.0f - fD) * 0.5f, d01 = fD * 0.5f;
        float Cc1_0, Cc1_1, Cc1_2, Cc1_3;
        if (parity) {                   // odd s: B (*) h0
            Cc1_0 = b0 * d00; Cc1_1 = b0 * d01 + b1 * d00;
            Cc1_2 = b1 * d01 + b2 * d00; Cc1_3 = b2 * d01;
        } else {
            Cc1_0 = d00; Cc1_1 = d01; Cc1_2 = 0.f; Cc1_3 = 0.f;
        }

        const float* __restrict__ W = g_taps[s >> 1];
        float w0v = W[tid];
        float w1v = (tid >= 1) ? W[tid - 1] : 0.f;
        float w2v = (tid >= 2) ? W[tid - 2] : 0.f;
        float w3v = (tid >= 3) ? W[tid - 3] : 0.f;
        const float tc0 = Cc0_0 * w0v + Cc0_1 * w1v + Cc0_2 * w2v + Cc0_3 * w3v;
        const float tc1 = Cc1_0 * w0v + Cc1_1 * w1v + Cc1_2 * w2v + Cc1_3 * w3v;
        taps01[tid] = parity ? make_float2(tc1, tc0) : make_float2(tc0, tc1);
    }
    __syncthreads();

    const int wm   = (w0 > w1) ? w0 : w1;
    const int supm = wm + 255;
    const int w6   = ((wm + 5) / 6) * 6;   // <= 126; taps zero beyond widths

    uint64_t A0a = 0ull, A1a = 0ull, A2a = 0ull;  // taps j..j+2
    uint64_t A0b = 0ull, A1b = 0ull, A2b = 0ull;  // taps j+3..j+5

    if (3 * (tid & ~31) < supm) {       // warp-uniform skip of dead warps
        const float* pp = &est[134 + 3 * tid];
        const uint64_t* __restrict__ tp = (const uint64_t*)taps01;
        for (int j = 0; j < w6; j += 6) {
            const uint64_t h0 = tp[j],     h1 = tp[j + 1], h2 = tp[j + 2];
            const uint64_t h3 = tp[j + 3], h4 = tp[j + 4], h5 = tp[j + 5];
            uint64_t pe2, pe1, pe0, pm1, pm2, pm3, pm4, pm5;
            PK2(pe2, pp[2]);  PK2(pe1, pp[1]);  PK2(pe0, pp[0]);
            PK2(pm1, pp[-1]); PK2(pm2, pp[-2]); PK2(pm3, pp[-3]);
            PK2(pm4, pp[-4]); PK2(pm5, pp[-5]);
            FMA2(A0a, h0, pe0); FMA2(A0a, h1, pm1); FMA2(A0a, h2, pm2);
            FMA2(A0b, h3, pm3); FMA2(A0b, h4, pm4); FMA2(A0b, h5, pm5);
            FMA2(A1a, h0, pe1); FMA2(A1a, h1, pe0); FMA2(A1a, h2, pm1);
            FMA2(A1b, h3, pm2); FMA2(A1b, h4, pm3); FMA2(A1b, h5, pm4);
            FMA2(A2a, h0, pe2); FMA2(A2a, h1, pe1); FMA2(A2a, h2, pe0);
            FMA2(A2b, h3, pm1); FMA2(A2b, h4, pm2); FMA2(A2b, h5, pm3);
            pp -= 6;
        }
    }

    uint64_t AB0, AB1, AB2;
    ADD2(AB0, A0a, A0b); ADD2(AB1, A1a, A1b); ADD2(AB2, A2a, A2b);
    float A0, A1, A2, B0, B1, B2;
    UNPK2(A0, B0, AB0); UNPK2(A1, B1, AB1); UNPK2(A2, B2, AB2);

    const int o0 = 3 * tid;
    {
        const int sup0 = w0 + 255;
        float* __restrict__ row = out + (size_t)b * T;           // sl row
        const int t0 = off0 + o0;
        if (o0     < sup0 && t0     < T) atomicAdd(&row[t0],     A0);
        if (o0 + 1 < sup0 && t0 + 1 < T) atomicAdd(&row[t0 + 1], A1);
        if (o0 + 2 < sup0 && t0 + 2 < T) atomicAdd(&row[t0 + 2], A2);
    }
    {
        const int sup1 = w1 + 255;
        float* __restrict__ row = out + (size_t)(BATCH + b) * T; // sr row
        const int t0 = off1 + o0;
        if (o0     < sup1 && t0     < T) atomicAdd(&row[t0],     B0);
        if (o0 + 1 < sup1 && t0 + 1 < T) atomicAdd(&row[t0 + 1], B1);
        if (o0 + 2 < sup1 && t0 + 2 < T) atomicAdd(&row[t0 + 2], B2);
    }
}

extern "C" void kernel_launch(void* const* d_in, const int* in_sizes, int n_in,
                              void* d_out, int out_size)
{
    const int*   lengthp = (const int*)  d_in[0];
    const float* pluckp  = (const float*)d_in[1];
    const float* exc     = (const float*)d_in[2];
    const float* ngp     = (const float*)d_in[3];
    const float* bgp     = (const float*)d_in[4];
    float* out = (float*)d_out;

    const int T  = in_sizes[2] / BATCH;          // excitation is (8, T)
    const int n4 = out_size / 4;
    const int nfill = (n4 + FILLPB - 1) / FILLPB;

    rows_and_fill<<<NROWBLK + nfill, NTW>>>(lengthp, pluckp, ngp, bgp, out, n4, T);
    apply_window<<<BATCH * SMAX, NTW>>>(lengthp, pluckp, ngp, bgp, exc, out, T);
}